// round 9
// baseline (speedup 1.0000x reference)
#include <cuda_runtime.h>
#include <math.h>
#include <stdint.h>

// Shapes (fixed by the problem)
#define T_STEPS 32
#define NB      64
#define CDIM    512
#define F1DIM   2048
#define F2DIM   1024
#define F3DIM   512

typedef unsigned long long ull;

// ---------------- scratch (device globals; no allocation allowed) -------------
__device__ float g_F1[T_STEPS * NB * CDIM];
__device__ float g_H1[T_STEPS * NB * F1DIM];
__device__ float g_F2[T_STEPS * NB * F1DIM];
__device__ float g_H2[T_STEPS * NB * F2DIM];
__device__ float g_F3[T_STEPS * NB * F2DIM];
__device__ float g_H3[T_STEPS * NB * F3DIM];

__device__ __forceinline__ float sigmoid_acc(float w) {
    return 1.0f / (1.0f + expf(-w));
}

// ---------------------------------------------------------------------------
// Stage 1 (verbatim from passing R1/R7)
// ---------------------------------------------------------------------------
__global__ void stage1_kernel(const float* __restrict__ x,
                              const float* __restrict__ w_jeff,
                              const float* __restrict__ w_cc,
                              const float* __restrict__ w_sf0,
                              const float* __restrict__ w_sf1)
{
    int gw   = (blockIdx.x * blockDim.x + threadIdx.x) >> 5;
    int lane = threadIdx.x & 31;
    if (gw >= NB * CDIM) return;
    int n = gw / CDIM;
    int c = gw - n * CDIM;

    float wj0 = w_jeff[lane * 2 + 0];
    float wj1 = w_jeff[lane * 2 + 1];
    float wcc = w_cc[lane];
    float d0  = 1.0f - sigmoid_acc(w_sf0[0]);
    float d1  = 1.0f - sigmoid_acc(w_sf1[0]);
    const float invlif = 1.0f / 1.5f;

    float yf0 = 0.f, yf1 = 0.f;
    float v = 0.f, g = 0.f, vI = 0.f, fo = 0.f;

    const float* xb = x + (size_t)n * 2 * CDIM + c;
#pragma unroll
    for (int t = 0; t < T_STEPS; t++) {
        float x0 = xb[(size_t)t * NB * 2 * CDIM];
        float x1 = xb[(size_t)t * NB * 2 * CDIM + CDIM];
        yf0 = 0.5f * yf0 + x0;
        yf1 = 0.5f * yf1 + x1;
        float u = wj0 * yf0 + wj1 * yf1;
        v = v + (u - v) * invlif;
        float s = (v >= 1.0f) ? 1.0f : 0.0f;
        v = (v >= 1.0f) ? 0.0f : v;
        g = d0 * g + s;
        float r = g * wcc;
#pragma unroll
        for (int off = 16; off; off >>= 1)
            r += __shfl_xor_sync(0xffffffffu, r, off);
        vI += r;
        float s1 = (vI >= 1.0f) ? 1.0f : 0.0f;
        vI = (vI >= 1.0f) ? 0.0f : vI;
        fo = d1 * fo + s1;
        if (lane == 0)
            g_F1[((size_t)t * NB + n) * CDIM + c] = fo;
    }
}

// ---------------------------------------------------------------------------
// FP32 GEMM (NT), packed f32x2 FMA, bit-identical sequential-k chains.
// C[m][o] = sum_k A[o][k] * B[m][k]
// Tile: 64 (o) x 128 (m), BK=16, 256 threads, 8(o)x4(m) microtile.
// B stored PRE-DUPLICATED in SMEM (ull pairs) -> no movs in inner loop.
// ---------------------------------------------------------------------------
#define PADA  68      // floats per k-row of As (64 o + 4)
#define PADBU 130     // ull per k-row of BsU (128 m + 2)

#define FMA2(acc, a, b) \
    asm("fma.rn.f32x2 %0, %1, %2, %0;" : "+l"(acc) : "l"(a), "l"(b))
#define PACK_DUP(d, s) \
    asm("mov.b64 %0, {%1, %1};" : "=l"(d) : "f"(s))
#define UNPACK2(lo, hi, v) \
    asm("mov.b64 {%0, %1}, %2;" : "=f"(lo), "=f"(hi) : "l"(v))

__global__ void __launch_bounds__(256, 2)
gemm_x2_kernel(const float* __restrict__ A, const float* __restrict__ B,
               float* __restrict__ C, int Mo, int K)
{
    __shared__ float As[2][16 * PADA];
    __shared__ ull   BsU[2][16 * PADBU];

    int tid = threadIdx.x;
    int ty  = tid & 7;          // o-microtile (0..7)  -> o = bo + ty*8
    int tx  = tid >> 3;         // m-microtile (0..31) -> m = bn + tx*4 + j
    int bo  = blockIdx.x * 64;
    int bn  = blockIdx.y * 128;
    int NC  = K / 16;

    // Loader roles
    int ao  = tid >> 2;         // A row (0..63)
    int af4 = tid & 3;          // A float4 column
    const float* gA = A + (size_t)(bo + ao) * K + af4 * 4;
    int bm0 = tid >> 1;         // B rows handled: pattern below
    (void)bm0;

    ull acc[4][4];
#pragma unroll
    for (int i = 0; i < 4; i++)
#pragma unroll
        for (int j = 0; j < 4; j++) acc[i][j] = 0ULL;

    float4 vA, vB0, vB1;
    int bmA = (tid) >> 2;            // reuse: B idx0 = tid -> m=tid>>2? see below
    (void)bmA;
    // B loader: two float4 per thread: idx = tid + p*256; m = idx>>2, f4 = idx&3
    const float* gB0 = B + (size_t)(bn + (tid >> 2)) * K + (tid & 3) * 4;
    const float* gB1 = B + (size_t)(bn + ((tid + 256) >> 2)) * K + (tid & 3) * 4;

    // prologue: chunk 0
    vA  = *(const float4*)(gA);
    vB0 = *(const float4*)(gB0);
    vB1 = *(const float4*)(gB1);

    for (int c = 0; c < NC; c++) {
        int buf = c & 1;
        // store chunk c
        {
            float* colA = &As[buf][af4 * 4 * PADA + ao];
            colA[0 * PADA] = vA.x; colA[1 * PADA] = vA.y;
            colA[2 * PADA] = vA.z; colA[3 * PADA] = vA.w;

            ull d0, d1, d2, d3;
            int m0 = tid >> 2, f40 = tid & 3;
            PACK_DUP(d0, vB0.x); PACK_DUP(d1, vB0.y);
            PACK_DUP(d2, vB0.z); PACK_DUP(d3, vB0.w);
            ull* colB0 = &BsU[buf][f40 * 4 * PADBU + m0];
            colB0[0 * PADBU] = d0; colB0[1 * PADBU] = d1;
            colB0[2 * PADBU] = d2; colB0[3 * PADBU] = d3;

            int m1 = (tid + 256) >> 2;
            PACK_DUP(d0, vB1.x); PACK_DUP(d1, vB1.y);
            PACK_DUP(d2, vB1.z); PACK_DUP(d3, vB1.w);
            ull* colB1 = &BsU[buf][f40 * 4 * PADBU + m1];
            colB1[0 * PADBU] = d0; colB1[1 * PADBU] = d1;
            colB1[2 * PADBU] = d2; colB1[3 * PADBU] = d3;
        }
        __syncthreads();

        // prefetch chunk c+1 into regs
        if (c + 1 < NC) {
            vA  = *(const float4*)(gA + (c + 1) * 16);
            vB0 = *(const float4*)(gB0 + (c + 1) * 16);
            vB1 = *(const float4*)(gB1 + (c + 1) * 16);
        }

        // compute chunk c
#pragma unroll
        for (int k = 0; k < 16; k++) {
            const float* as = &As[buf][k * PADA + ty * 8];
            ulonglong2 t0 = *(const ulonglong2*)as;        // o-pairs (0,1),(2,3)
            ulonglong2 t1 = *(const ulonglong2*)(as + 4);  // (4,5),(6,7)
            const ull* bs = &BsU[buf][k * PADBU + tx * 4];
            ulonglong2 u0 = *(const ulonglong2*)bs;        // dup m+0, m+1
            ulonglong2 u1 = *(const ulonglong2*)(bs + 2);  // dup m+2, m+3
            ull aP[4] = {t0.x, t0.y, t1.x, t1.y};
            ull bb[4] = {u0.x, u0.y, u1.x, u1.y};
#pragma unroll
            for (int j = 0; j < 4; j++)
#pragma unroll
                for (int i = 0; i < 4; i++)
                    FMA2(acc[i][j], aP[i], bb[j]);
        }
        __syncthreads();
    }

    // epilogue: m = bn + tx*4 + j, cols o = bo + ty*8 .. +7
#pragma unroll
    for (int j = 0; j < 4; j++) {
        float r0, r1, r2, r3, r4, r5, r6, r7;
        UNPACK2(r0, r1, acc[0][j]);
        UNPACK2(r2, r3, acc[1][j]);
        UNPACK2(r4, r5, acc[2][j]);
        UNPACK2(r6, r7, acc[3][j]);
        float* cp = C + (size_t)(bn + tx * 4 + j) * Mo + bo + ty * 8;
        *reinterpret_cast<float4*>(cp + 0) = make_float4(r0, r1, r2, r3);
        *reinterpret_cast<float4*>(cp + 4) = make_float4(r4, r5, r6, r7);
    }
}

// ---------------------------------------------------------------------------
// IFNode + SynapseFilter fused (verbatim from R1/R7).
// ---------------------------------------------------------------------------
__global__ void ifsyn_kernel(const float* __restrict__ H, float* __restrict__ F,
                             const float* __restrict__ w_sf, int Odim)
{
    int idx = blockIdx.x * blockDim.x + threadIdx.x;
    if (idx >= NB * Odim) return;
    int o = idx % Odim;
    int n = idx / Odim;
    float d = 1.0f - sigmoid_acc(w_sf[0]);
    float v = 0.f, f = 0.f;
#pragma unroll
    for (int t = 0; t < T_STEPS; t++) {
        size_t id = ((size_t)t * NB + n) * Odim + o;
        v += H[id];
        float s = (v >= 1.0f) ? 1.0f : 0.0f;
        v = (v >= 1.0f) ? 0.0f : v;
        f = d * f + s;
        F[id] = f;
    }
}

// ---------------------------------------------------------------------------
// Final kernel (verbatim from R1/R7).
// ---------------------------------------------------------------------------
__global__ void final_kernel(const float* __restrict__ Wout,
                             const float* __restrict__ bout,
                             float* __restrict__ out)
{
    int n = blockIdx.x;
    int f = threadIdx.x;
    __shared__ float red[16];
    float v   = 0.f;
    float wf  = Wout[f];
    float acc = 0.f;
    float b   = bout[0];
    int lane = f & 31, wid = f >> 5;
    for (int t = 0; t < T_STEPS; t++) {
        v += g_H3[((size_t)t * NB + n) * F3DIM + f];
        float s = (v >= 1.0f) ? 1.0f : 0.0f;
        v = (v >= 1.0f) ? 0.0f : v;
        float p = wf * s;
#pragma unroll
        for (int off = 16; off; off >>= 1)
            p += __shfl_xor_sync(0xffffffffu, p, off);
        if (lane == 0) red[wid] = p;
        __syncthreads();
        if (f < 16) {
            float q = red[f];
#pragma unroll
            for (int off = 8; off; off >>= 1)
                q += __shfl_xor_sync(0x0000ffffu, q, off);
            if (f == 0) {
                acc += q + b;
                out[t * NB + n] = acc;
            }
        }
        __syncthreads();
    }
}

// ---------------------------------------------------------------------------
extern "C" void kernel_launch(void* const* d_in, const int* in_sizes, int n_in,
                              void* d_out, int out_size)
{
    (void)in_sizes; (void)n_in; (void)out_size;
    const float* x     = (const float*)d_in[0];
    const float* wjeff = (const float*)d_in[1];
    const float* wcc   = (const float*)d_in[2];
    const float* wsf0  = (const float*)d_in[3];
    const float* W1    = (const float*)d_in[4];
    const float* wsf1  = (const float*)d_in[5];
    const float* W2    = (const float*)d_in[6];
    const float* wsf2  = (const float*)d_in[7];
    const float* W3    = (const float*)d_in[8];
    const float* wsf3  = (const float*)d_in[9];
    const float* Wout  = (const float*)d_in[10];
    const float* bout  = (const float*)d_in[11];
    float* out = (float*)d_out;

    float *F1, *H1, *F2, *H2, *F3, *H3;
    cudaGetSymbolAddress((void**)&F1, g_F1);
    cudaGetSymbolAddress((void**)&H1, g_H1);
    cudaGetSymbolAddress((void**)&F2, g_F2);
    cudaGetSymbolAddress((void**)&H2, g_H2);
    cudaGetSymbolAddress((void**)&F3, g_F3);
    cudaGetSymbolAddress((void**)&H3, g_H3);

    // Stage 1
    stage1_kernel<<<(NB * CDIM * 32) / 256, 256>>>(x, wjeff, wcc, wsf0, wsf1);

    // Block 1: grid (32,16)=512
    gemm_x2_kernel<<<dim3(F1DIM / 64, (T_STEPS * NB) / 128), 256>>>(W1, F1, H1, F1DIM, CDIM);
    ifsyn_kernel<<<(NB * F1DIM + 255) / 256, 256>>>(H1, F2, wsf2, F1DIM);

    // Block 2: grid (16,16)=256
    gemm_x2_kernel<<<dim3(F2DIM / 64, (T_STEPS * NB) / 128), 256>>>(W2, F2, H2, F2DIM, F1DIM);
    ifsyn_kernel<<<(NB * F2DIM + 255) / 256, 256>>>(H2, F3, wsf3, F2DIM);

    // Block 3: grid (8,16)=128
    gemm_x2_kernel<<<dim3(F3DIM / 64, (T_STEPS * NB) / 128), 256>>>(W3, F3, H3, F3DIM, F2DIM);

    // Final linear + NonSpikingIF cumsum
    final_kernel<<<NB, F3DIM>>>(Wout, bout, out);
}

// round 10
// speedup vs baseline: 1.3765x; 1.3765x over previous
#include <cuda_runtime.h>
#include <math.h>
#include <stdint.h>

// Shapes (fixed by the problem)
#define T_STEPS 32
#define NB      64
#define CDIM    512
#define F1DIM   2048
#define F2DIM   1024
#define F3DIM   512

typedef unsigned long long ull;

// ---------------- scratch (device globals; no allocation allowed) -------------
__device__ float g_F1[T_STEPS * NB * CDIM];
__device__ float g_H1[T_STEPS * NB * F1DIM];
__device__ float g_F2[T_STEPS * NB * F1DIM];
__device__ float g_H2[T_STEPS * NB * F2DIM];
__device__ float g_F3[T_STEPS * NB * F2DIM];
__device__ float g_H3[T_STEPS * NB * F3DIM];

__device__ __forceinline__ float sigmoid_acc(float w) {
    return 1.0f / (1.0f + expf(-w));
}

// ---------------------------------------------------------------------------
// Stage 1 (verbatim from passing R1/R7)
// ---------------------------------------------------------------------------
__global__ void stage1_kernel(const float* __restrict__ x,
                              const float* __restrict__ w_jeff,
                              const float* __restrict__ w_cc,
                              const float* __restrict__ w_sf0,
                              const float* __restrict__ w_sf1)
{
    int gw   = (blockIdx.x * blockDim.x + threadIdx.x) >> 5;
    int lane = threadIdx.x & 31;
    if (gw >= NB * CDIM) return;
    int n = gw / CDIM;
    int c = gw - n * CDIM;

    float wj0 = w_jeff[lane * 2 + 0];
    float wj1 = w_jeff[lane * 2 + 1];
    float wcc = w_cc[lane];
    float d0  = 1.0f - sigmoid_acc(w_sf0[0]);
    float d1  = 1.0f - sigmoid_acc(w_sf1[0]);
    const float invlif = 1.0f / 1.5f;

    float yf0 = 0.f, yf1 = 0.f;
    float v = 0.f, g = 0.f, vI = 0.f, fo = 0.f;

    const float* xb = x + (size_t)n * 2 * CDIM + c;
#pragma unroll
    for (int t = 0; t < T_STEPS; t++) {
        float x0 = xb[(size_t)t * NB * 2 * CDIM];
        float x1 = xb[(size_t)t * NB * 2 * CDIM + CDIM];
        yf0 = 0.5f * yf0 + x0;
        yf1 = 0.5f * yf1 + x1;
        float u = wj0 * yf0 + wj1 * yf1;
        v = v + (u - v) * invlif;
        float s = (v >= 1.0f) ? 1.0f : 0.0f;
        v = (v >= 1.0f) ? 0.0f : v;
        g = d0 * g + s;
        float r = g * wcc;
#pragma unroll
        for (int off = 16; off; off >>= 1)
            r += __shfl_xor_sync(0xffffffffu, r, off);
        vI += r;
        float s1 = (vI >= 1.0f) ? 1.0f : 0.0f;
        vI = (vI >= 1.0f) ? 0.0f : vI;
        fo = d1 * fo + s1;
        if (lane == 0)
            g_F1[((size_t)t * NB + n) * CDIM + c] = fo;
    }
}

// ---------------------------------------------------------------------------
// FP32 GEMM (NT), packed f32x2 FMA, bit-identical sequential-k chains.
// C[m][o] = sum_k A[o][k] * B[m][k]
// Tile: 64 (o) x 128 (m), BK=16, 256 threads, microtile 4(o) x 8(m).
// Accumulators pair (m, m+1): B operand is a DIRECT contiguous ull pair
// (no duplication); only 4 A scalars/k are mov-duplicated.
// ---------------------------------------------------------------------------
#define PADA 68     // floats per k-row of As (64 o + 4)
#define PADB 132    // floats per k-row of Bs (128 m + 4)

#define FMA2(acc, a, b) \
    asm("fma.rn.f32x2 %0, %1, %2, %0;" : "+l"(acc) : "l"(a), "l"(b))
#define PACK_DUP(d, s) \
    asm("mov.b64 %0, {%1, %1};" : "=l"(d) : "f"(s))
#define UNPACK2(lo, hi, v) \
    asm("mov.b64 {%0, %1}, %2;" : "=f"(lo), "=f"(hi) : "l"(v))

__global__ void __launch_bounds__(256, 2)
gemm_x2_kernel(const float* __restrict__ A, const float* __restrict__ B,
               float* __restrict__ C, int Mo, int K)
{
    __shared__ float As[2][16 * PADA];
    __shared__ float Bs[2][16 * PADB];

    int tid = threadIdx.x;
    int ty  = tid & 15;          // o-microtile (0..15): o = bo + ty*4
    int tx  = tid >> 4;          // m-microtile (0..15): m = bn + tx*8
    int bo  = blockIdx.x * 64;
    int bn  = blockIdx.y * 128;
    int NC  = K / 16;

    // Loader roles
    int ao  = tid & 63;          // A row (o)
    int af  = tid >> 6;          // A float4 col (0..3)
    const float* gA = A + (size_t)(bo + ao) * K + af * 4;
    int bi0 = tid,      bm0 = bi0 & 127, bf0 = bi0 >> 7;   // B f4 #1
    int bi1 = tid + 256, bm1 = bi1 & 127, bf1 = bi1 >> 7;  // B f4 #2
    const float* gB0 = B + (size_t)(bn + bm0) * K + bf0 * 4;
    const float* gB1 = B + (size_t)(bn + bm1) * K + bf1 * 4;

    ull acc[4][4];               // [o][m-pair]
#pragma unroll
    for (int i = 0; i < 4; i++)
#pragma unroll
        for (int j = 0; j < 4; j++) acc[i][j] = 0ULL;

    float4 vA, vB0, vB1;
    vA  = *(const float4*)(gA);
    vB0 = *(const float4*)(gB0);
    vB1 = *(const float4*)(gB1);

    for (int c = 0; c < NC; c++) {
        int buf = c & 1;
        // store chunk c (transpose to [k][row])
        {
            float* colA = &As[buf][(af * 4) * PADA + ao];
            colA[0 * PADA] = vA.x; colA[1 * PADA] = vA.y;
            colA[2 * PADA] = vA.z; colA[3 * PADA] = vA.w;
            float* colB0 = &Bs[buf][(bf0 * 4) * PADB + bm0];
            colB0[0 * PADB] = vB0.x; colB0[1 * PADB] = vB0.y;
            colB0[2 * PADB] = vB0.z; colB0[3 * PADB] = vB0.w;
            float* colB1 = &Bs[buf][(bf1 * 4) * PADB + bm1];
            colB1[0 * PADB] = vB1.x; colB1[1 * PADB] = vB1.y;
            colB1[2 * PADB] = vB1.z; colB1[3 * PADB] = vB1.w;
        }
        __syncthreads();

        // prefetch chunk c+1
        if (c + 1 < NC) {
            vA  = *(const float4*)(gA + (c + 1) * 16);
            vB0 = *(const float4*)(gB0 + (c + 1) * 16);
            vB1 = *(const float4*)(gB1 + (c + 1) * 16);
        }

        // compute chunk c
#pragma unroll
        for (int k = 0; k < 16; k++) {
            const float* as = &As[buf][k * PADA + ty * 4];
            const float* bs = &Bs[buf][k * PADB + tx * 8];
            float4 av = *(const float4*)as;              // 4 o weights
            ulonglong2 u0 = *(const ulonglong2*)bs;      // (m0,m1),(m2,m3)
            ulonglong2 u1 = *(const ulonglong2*)(bs + 4);// (m4,m5),(m6,m7)
            ull aD[4];
            PACK_DUP(aD[0], av.x); PACK_DUP(aD[1], av.y);
            PACK_DUP(aD[2], av.z); PACK_DUP(aD[3], av.w);
            ull bP[4] = {u0.x, u0.y, u1.x, u1.y};
#pragma unroll
            for (int i = 0; i < 4; i++)
#pragma unroll
                for (int j = 0; j < 4; j++)
                    FMA2(acc[i][j], aD[i], bP[j]);
        }
        __syncthreads();
    }

    // Epilogue: acc[i][j] = (C[m][o], C[m+1][o]) for m = bn+tx*8+j*2, o = bo+ty*4+i
#pragma unroll
    for (int j = 0; j < 4; j++) {
        float lo0, hi0, lo1, hi1, lo2, hi2, lo3, hi3;
        UNPACK2(lo0, hi0, acc[0][j]);
        UNPACK2(lo1, hi1, acc[1][j]);
        UNPACK2(lo2, hi2, acc[2][j]);
        UNPACK2(lo3, hi3, acc[3][j]);
        int m = bn + tx * 8 + j * 2;
        float* cp0 = C + (size_t)m * Mo + bo + ty * 4;
        float* cp1 = C + (size_t)(m + 1) * Mo + bo + ty * 4;
        *reinterpret_cast<float4*>(cp0) = make_float4(lo0, lo1, lo2, lo3);
        *reinterpret_cast<float4*>(cp1) = make_float4(hi0, hi1, hi2, hi3);
    }
}

// ---------------------------------------------------------------------------
// IFNode + SynapseFilter fused (verbatim from R1/R7).
// ---------------------------------------------------------------------------
__global__ void ifsyn_kernel(const float* __restrict__ H, float* __restrict__ F,
                             const float* __restrict__ w_sf, int Odim)
{
    int idx = blockIdx.x * blockDim.x + threadIdx.x;
    if (idx >= NB * Odim) return;
    int o = idx % Odim;
    int n = idx / Odim;
    float d = 1.0f - sigmoid_acc(w_sf[0]);
    float v = 0.f, f = 0.f;
#pragma unroll
    for (int t = 0; t < T_STEPS; t++) {
        size_t id = ((size_t)t * NB + n) * Odim + o;
        v += H[id];
        float s = (v >= 1.0f) ? 1.0f : 0.0f;
        v = (v >= 1.0f) ? 0.0f : v;
        f = d * f + s;
        F[id] = f;
    }
}

// ---------------------------------------------------------------------------
// Final kernel (verbatim from R1/R7).
// ---------------------------------------------------------------------------
__global__ void final_kernel(const float* __restrict__ Wout,
                             const float* __restrict__ bout,
                             float* __restrict__ out)
{
    int n = blockIdx.x;
    int f = threadIdx.x;
    __shared__ float red[16];
    float v   = 0.f;
    float wf  = Wout[f];
    float acc = 0.f;
    float b   = bout[0];
    int lane = f & 31, wid = f >> 5;
    for (int t = 0; t < T_STEPS; t++) {
        v += g_H3[((size_t)t * NB + n) * F3DIM + f];
        float s = (v >= 1.0f) ? 1.0f : 0.0f;
        v = (v >= 1.0f) ? 0.0f : v;
        float p = wf * s;
#pragma unroll
        for (int off = 16; off; off >>= 1)
            p += __shfl_xor_sync(0xffffffffu, p, off);
        if (lane == 0) red[wid] = p;
        __syncthreads();
        if (f < 16) {
            float q = red[f];
#pragma unroll
            for (int off = 8; off; off >>= 1)
                q += __shfl_xor_sync(0x0000ffffu, q, off);
            if (f == 0) {
                acc += q + b;
                out[t * NB + n] = acc;
            }
        }
        __syncthreads();
    }
}

// ---------------------------------------------------------------------------
extern "C" void kernel_launch(void* const* d_in, const int* in_sizes, int n_in,
                              void* d_out, int out_size)
{
    (void)in_sizes; (void)n_in; (void)out_size;
    const float* x     = (const float*)d_in[0];
    const float* wjeff = (const float*)d_in[1];
    const float* wcc   = (const float*)d_in[2];
    const float* wsf0  = (const float*)d_in[3];
    const float* W1    = (const float*)d_in[4];
    const float* wsf1  = (const float*)d_in[5];
    const float* W2    = (const float*)d_in[6];
    const float* wsf2  = (const float*)d_in[7];
    const float* W3    = (const float*)d_in[8];
    const float* wsf3  = (const float*)d_in[9];
    const float* Wout  = (const float*)d_in[10];
    const float* bout  = (const float*)d_in[11];
    float* out = (float*)d_out;

    float *F1, *H1, *F2, *H2, *F3, *H3;
    cudaGetSymbolAddress((void**)&F1, g_F1);
    cudaGetSymbolAddress((void**)&H1, g_H1);
    cudaGetSymbolAddress((void**)&F2, g_F2);
    cudaGetSymbolAddress((void**)&H2, g_H2);
    cudaGetSymbolAddress((void**)&F3, g_F3);
    cudaGetSymbolAddress((void**)&H3, g_H3);

    // Stage 1
    stage1_kernel<<<(NB * CDIM * 32) / 256, 256>>>(x, wjeff, wcc, wsf0, wsf1);

    // Block 1: grid (32,16)=512
    gemm_x2_kernel<<<dim3(F1DIM / 64, (T_STEPS * NB) / 128), 256>>>(W1, F1, H1, F1DIM, CDIM);
    ifsyn_kernel<<<(NB * F1DIM + 255) / 256, 256>>>(H1, F2, wsf2, F1DIM);

    // Block 2: grid (16,16)=256
    gemm_x2_kernel<<<dim3(F2DIM / 64, (T_STEPS * NB) / 128), 256>>>(W2, F2, H2, F2DIM, F1DIM);
    ifsyn_kernel<<<(NB * F2DIM + 255) / 256, 256>>>(H2, F3, wsf3, F2DIM);

    // Block 3: grid (8,16)=128
    gemm_x2_kernel<<<dim3(F3DIM / 64, (T_STEPS * NB) / 128), 256>>>(W3, F3, H3, F3DIM, F2DIM);

    // Final linear + NonSpikingIF cumsum
    final_kernel<<<NB, F3DIM>>>(Wout, bout, out);
}

// round 11
// speedup vs baseline: 1.4384x; 1.0449x over previous
#include <cuda_runtime.h>
#include <math.h>
#include <stdint.h>

// Shapes (fixed by the problem)
#define T_STEPS 32
#define NB      64
#define CDIM    512
#define F1DIM   2048
#define F2DIM   1024
#define F3DIM   512

typedef unsigned long long ull;

// ---------------- scratch (device globals; no allocation allowed) -------------
__device__ float g_F1[T_STEPS * NB * CDIM];
__device__ float g_H1[T_STEPS * NB * F1DIM];
__device__ float g_F2[T_STEPS * NB * F1DIM];
__device__ float g_H2[T_STEPS * NB * F2DIM];
__device__ float g_F3[T_STEPS * NB * F2DIM];
__device__ float g_H3[T_STEPS * NB * F3DIM];

__device__ __forceinline__ float sigmoid_acc(float w) {
    return 1.0f / (1.0f + expf(-w));
}

// ---------------------------------------------------------------------------
// Stage 1 (verbatim from passing R1/R7)
// ---------------------------------------------------------------------------
__global__ void stage1_kernel(const float* __restrict__ x,
                              const float* __restrict__ w_jeff,
                              const float* __restrict__ w_cc,
                              const float* __restrict__ w_sf0,
                              const float* __restrict__ w_sf1)
{
    int gw   = (blockIdx.x * blockDim.x + threadIdx.x) >> 5;
    int lane = threadIdx.x & 31;
    if (gw >= NB * CDIM) return;
    int n = gw / CDIM;
    int c = gw - n * CDIM;

    float wj0 = w_jeff[lane * 2 + 0];
    float wj1 = w_jeff[lane * 2 + 1];
    float wcc = w_cc[lane];
    float d0  = 1.0f - sigmoid_acc(w_sf0[0]);
    float d1  = 1.0f - sigmoid_acc(w_sf1[0]);
    const float invlif = 1.0f / 1.5f;

    float yf0 = 0.f, yf1 = 0.f;
    float v = 0.f, g = 0.f, vI = 0.f, fo = 0.f;

    const float* xb = x + (size_t)n * 2 * CDIM + c;
#pragma unroll
    for (int t = 0; t < T_STEPS; t++) {
        float x0 = xb[(size_t)t * NB * 2 * CDIM];
        float x1 = xb[(size_t)t * NB * 2 * CDIM + CDIM];
        yf0 = 0.5f * yf0 + x0;
        yf1 = 0.5f * yf1 + x1;
        float u = wj0 * yf0 + wj1 * yf1;
        v = v + (u - v) * invlif;
        float s = (v >= 1.0f) ? 1.0f : 0.0f;
        v = (v >= 1.0f) ? 0.0f : v;
        g = d0 * g + s;
        float r = g * wcc;
#pragma unroll
        for (int off = 16; off; off >>= 1)
            r += __shfl_xor_sync(0xffffffffu, r, off);
        vI += r;
        float s1 = (vI >= 1.0f) ? 1.0f : 0.0f;
        vI = (vI >= 1.0f) ? 0.0f : vI;
        fo = d1 * fo + s1;
        if (lane == 0)
            g_F1[((size_t)t * NB + n) * CDIM + c] = fo;
    }
}

// ---------------------------------------------------------------------------
// FP32 GEMM (NT), packed f32x2 FMA, bit-identical sequential-k chains.
// C[m][o] = sum_k A[o][k] * B[m][k]
// Tile: 64 (o) x 128 (m), BK=32, 256 threads, microtile 4(o) x 8(m),
// m-paired accumulators. Double-buffered SMEM, ONE barrier per 32-k chunk.
// ---------------------------------------------------------------------------
#define PADA 68     // floats per k-row of As (64 o + 4)
#define PADB 132    // floats per k-row of Bs (128 m + 4)
#define ABUF (32 * PADA)          // floats per A buffer
#define BBUF (32 * PADB)          // floats per B buffer
#define SMEM_FLOATS (2 * ABUF + 2 * BBUF)
#define SMEM_BYTES  (SMEM_FLOATS * 4)   // 51200

#define FMA2(acc, a, b) \
    asm("fma.rn.f32x2 %0, %1, %2, %0;" : "+l"(acc) : "l"(a), "l"(b))
#define PACK_DUP(d, s) \
    asm("mov.b64 %0, {%1, %1};" : "=l"(d) : "f"(s))
#define UNPACK2(lo, hi, v) \
    asm("mov.b64 {%0, %1}, %2;" : "=f"(lo), "=f"(hi) : "l"(v))

__global__ void __launch_bounds__(256, 2)
gemm_x2_kernel(const float* __restrict__ A, const float* __restrict__ B,
               float* __restrict__ C, int Mo, int K)
{
    extern __shared__ float smem[];
    float* Asm = smem;                    // [2][32*PADA]
    float* Bsm = smem + 2 * ABUF;         // [2][32*PADB]

    int tid = threadIdx.x;
    int ty  = tid & 15;          // o-microtile: o = bo + ty*4
    int tx  = tid >> 4;          // m-microtile: m = bn + tx*8
    int bo  = blockIdx.x * 64;
    int bn  = blockIdx.y * 128;
    int NC  = K / 32;

    // Loader roles (BK=32)
    int ao = tid & 63;           // A row (o);  cols: af*4 and af*4+16
    int af = tid >> 6;           // 0..3
    const float* gA = A + (size_t)(bo + ao) * K + af * 4;
    int bm = tid & 127;          // B row (m);  cols: bf*4 + {0,8,16,24}
    int bf = tid >> 7;           // 0..1
    const float* gB = B + (size_t)(bn + bm) * K + bf * 4;

    ull acc[4][4];               // [o][m-pair]
#pragma unroll
    for (int i = 0; i < 4; i++)
#pragma unroll
        for (int j = 0; j < 4; j++) acc[i][j] = 0ULL;

    float4 vA0, vA1, vB0, vB1, vB2, vB3;

    // load chunk 0
    vA0 = *(const float4*)(gA);
    vA1 = *(const float4*)(gA + 16);
    vB0 = *(const float4*)(gB);
    vB1 = *(const float4*)(gB + 8);
    vB2 = *(const float4*)(gB + 16);
    vB3 = *(const float4*)(gB + 24);

    // store chunk 0 into buffer 0 (transpose to [k][row])
    {
        float* cA = &Asm[(af * 4) * PADA + ao];
        cA[0 * PADA] = vA0.x; cA[1 * PADA] = vA0.y;
        cA[2 * PADA] = vA0.z; cA[3 * PADA] = vA0.w;
        float* cA2 = cA + 16 * PADA;
        cA2[0 * PADA] = vA1.x; cA2[1 * PADA] = vA1.y;
        cA2[2 * PADA] = vA1.z; cA2[3 * PADA] = vA1.w;
        float* cB = &Bsm[(bf * 4) * PADB + bm];
        cB[0 * PADB] = vB0.x; cB[1 * PADB] = vB0.y;
        cB[2 * PADB] = vB0.z; cB[3 * PADB] = vB0.w;
        float* p = cB + 8 * PADB;
        p[0 * PADB] = vB1.x; p[1 * PADB] = vB1.y;
        p[2 * PADB] = vB1.z; p[3 * PADB] = vB1.w;
        p = cB + 16 * PADB;
        p[0 * PADB] = vB2.x; p[1 * PADB] = vB2.y;
        p[2 * PADB] = vB2.z; p[3 * PADB] = vB2.w;
        p = cB + 24 * PADB;
        p[0 * PADB] = vB3.x; p[1 * PADB] = vB3.y;
        p[2 * PADB] = vB3.z; p[3 * PADB] = vB3.w;
    }
    __syncthreads();

    for (int c = 0; c < NC; c++) {
        int buf = c & 1;
        // prefetch chunk c+1 into regs (overlaps compute below)
        if (c + 1 < NC) {
            const float* pA = gA + (c + 1) * 32;
            const float* pB = gB + (c + 1) * 32;
            vA0 = *(const float4*)(pA);
            vA1 = *(const float4*)(pA + 16);
            vB0 = *(const float4*)(pB);
            vB1 = *(const float4*)(pB + 8);
            vB2 = *(const float4*)(pB + 16);
            vB3 = *(const float4*)(pB + 24);
        }

        // compute chunk c (32 k-steps, sequential order per output chain)
        const float* Ab = Asm + buf * ABUF;
        const float* Bb = Bsm + buf * BBUF;
#pragma unroll
        for (int k = 0; k < 32; k++) {
            const float* as = Ab + k * PADA + ty * 4;
            const float* bs = Bb + k * PADB + tx * 8;
            float4 av = *(const float4*)as;               // 4 o weights
            ulonglong2 u0 = *(const ulonglong2*)bs;       // (m0,m1),(m2,m3)
            ulonglong2 u1 = *(const ulonglong2*)(bs + 4); // (m4,m5),(m6,m7)
            ull aD[4];
            PACK_DUP(aD[0], av.x); PACK_DUP(aD[1], av.y);
            PACK_DUP(aD[2], av.z); PACK_DUP(aD[3], av.w);
            ull bP[4] = {u0.x, u0.y, u1.x, u1.y};
#pragma unroll
            for (int i = 0; i < 4; i++)
#pragma unroll
                for (int j = 0; j < 4; j++)
                    FMA2(acc[i][j], aD[i], bP[j]);
        }

        // store chunk c+1 into the other buffer; ONE barrier per chunk
        if (c + 1 < NC) {
            float* Aw = Asm + (buf ^ 1) * ABUF;
            float* Bw = Bsm + (buf ^ 1) * BBUF;
            float* cA = &Aw[(af * 4) * PADA + ao];
            cA[0 * PADA] = vA0.x; cA[1 * PADA] = vA0.y;
            cA[2 * PADA] = vA0.z; cA[3 * PADA] = vA0.w;
            float* cA2 = cA + 16 * PADA;
            cA2[0 * PADA] = vA1.x; cA2[1 * PADA] = vA1.y;
            cA2[2 * PADA] = vA1.z; cA2[3 * PADA] = vA1.w;
            float* cB = &Bw[(bf * 4) * PADB + bm];
            cB[0 * PADB] = vB0.x; cB[1 * PADB] = vB0.y;
            cB[2 * PADB] = vB0.z; cB[3 * PADB] = vB0.w;
            float* p = cB + 8 * PADB;
            p[0 * PADB] = vB1.x; p[1 * PADB] = vB1.y;
            p[2 * PADB] = vB1.z; p[3 * PADB] = vB1.w;
            p = cB + 16 * PADB;
            p[0 * PADB] = vB2.x; p[1 * PADB] = vB2.y;
            p[2 * PADB] = vB2.z; p[3 * PADB] = vB2.w;
            p = cB + 24 * PADB;
            p[0 * PADB] = vB3.x; p[1 * PADB] = vB3.y;
            p[2 * PADB] = vB3.z; p[3 * PADB] = vB3.w;
            __syncthreads();
        }
    }

    // Epilogue: acc[i][j] = (C[m][o], C[m+1][o]), m = bn+tx*8+j*2, o = bo+ty*4+i
#pragma unroll
    for (int j = 0; j < 4; j++) {
        float lo0, hi0, lo1, hi1, lo2, hi2, lo3, hi3;
        UNPACK2(lo0, hi0, acc[0][j]);
        UNPACK2(lo1, hi1, acc[1][j]);
        UNPACK2(lo2, hi2, acc[2][j]);
        UNPACK2(lo3, hi3, acc[3][j]);
        int m = bn + tx * 8 + j * 2;
        float* cp0 = C + (size_t)m * Mo + bo + ty * 4;
        float* cp1 = C + (size_t)(m + 1) * Mo + bo + ty * 4;
        *reinterpret_cast<float4*>(cp0) = make_float4(lo0, lo1, lo2, lo3);
        *reinterpret_cast<float4*>(cp1) = make_float4(hi0, hi1, hi2, hi3);
    }
}

// ---------------------------------------------------------------------------
// IFNode + SynapseFilter fused (verbatim from R1/R7).
// ---------------------------------------------------------------------------
__global__ void ifsyn_kernel(const float* __restrict__ H, float* __restrict__ F,
                             const float* __restrict__ w_sf, int Odim)
{
    int idx = blockIdx.x * blockDim.x + threadIdx.x;
    if (idx >= NB * Odim) return;
    int o = idx % Odim;
    int n = idx / Odim;
    float d = 1.0f - sigmoid_acc(w_sf[0]);
    float v = 0.f, f = 0.f;
#pragma unroll
    for (int t = 0; t < T_STEPS; t++) {
        size_t id = ((size_t)t * NB + n) * Odim + o;
        v += H[id];
        float s = (v >= 1.0f) ? 1.0f : 0.0f;
        v = (v >= 1.0f) ? 0.0f : v;
        f = d * f + s;
        F[id] = f;
    }
}

// ---------------------------------------------------------------------------
// Final kernel (verbatim from R1/R7).
// ---------------------------------------------------------------------------
__global__ void final_kernel(const float* __restrict__ Wout,
                             const float* __restrict__ bout,
                             float* __restrict__ out)
{
    int n = blockIdx.x;
    int f = threadIdx.x;
    __shared__ float red[16];
    float v   = 0.f;
    float wf  = Wout[f];
    float acc = 0.f;
    float b   = bout[0];
    int lane = f & 31, wid = f >> 5;
    for (int t = 0; t < T_STEPS; t++) {
        v += g_H3[((size_t)t * NB + n) * F3DIM + f];
        float s = (v >= 1.0f) ? 1.0f : 0.0f;
        v = (v >= 1.0f) ? 0.0f : v;
        float p = wf * s;
#pragma unroll
        for (int off = 16; off; off >>= 1)
            p += __shfl_xor_sync(0xffffffffu, p, off);
        if (lane == 0) red[wid] = p;
        __syncthreads();
        if (f < 16) {
            float q = red[f];
#pragma unroll
            for (int off = 8; off; off >>= 1)
                q += __shfl_xor_sync(0x0000ffffu, q, off);
            if (f == 0) {
                acc += q + b;
                out[t * NB + n] = acc;
            }
        }
        __syncthreads();
    }
}

// ---------------------------------------------------------------------------
extern "C" void kernel_launch(void* const* d_in, const int* in_sizes, int n_in,
                              void* d_out, int out_size)
{
    (void)in_sizes; (void)n_in; (void)out_size;
    const float* x     = (const float*)d_in[0];
    const float* wjeff = (const float*)d_in[1];
    const float* wcc   = (const float*)d_in[2];
    const float* wsf0  = (const float*)d_in[3];
    const float* W1    = (const float*)d_in[4];
    const float* wsf1  = (const float*)d_in[5];
    const float* W2    = (const float*)d_in[6];
    const float* wsf2  = (const float*)d_in[7];
    const float* W3    = (const float*)d_in[8];
    const float* wsf3  = (const float*)d_in[9];
    const float* Wout  = (const float*)d_in[10];
    const float* bout  = (const float*)d_in[11];
    float* out = (float*)d_out;

    float *F1, *H1, *F2, *H2, *F3, *H3;
    cudaGetSymbolAddress((void**)&F1, g_F1);
    cudaGetSymbolAddress((void**)&H1, g_H1);
    cudaGetSymbolAddress((void**)&F2, g_F2);
    cudaGetSymbolAddress((void**)&H2, g_H2);
    cudaGetSymbolAddress((void**)&F3, g_F3);
    cudaGetSymbolAddress((void**)&H3, g_H3);

    cudaFuncSetAttribute(gemm_x2_kernel,
                         cudaFuncAttributeMaxDynamicSharedMemorySize, SMEM_BYTES);

    // Stage 1
    stage1_kernel<<<(NB * CDIM * 32) / 256, 256>>>(x, wjeff, wcc, wsf0, wsf1);

    // Block 1: grid (32,16)=512
    gemm_x2_kernel<<<dim3(F1DIM / 64, (T_STEPS * NB) / 128), 256, SMEM_BYTES>>>(W1, F1, H1, F1DIM, CDIM);
    ifsyn_kernel<<<(NB * F1DIM + 255) / 256, 256>>>(H1, F2, wsf2, F1DIM);

    // Block 2: grid (16,16)=256
    gemm_x2_kernel<<<dim3(F2DIM / 64, (T_STEPS * NB) / 128), 256, SMEM_BYTES>>>(W2, F2, H2, F2DIM, F1DIM);
    ifsyn_kernel<<<(NB * F2DIM + 255) / 256, 256>>>(H2, F3, wsf3, F2DIM);

    // Block 3: grid (8,16)=128
    gemm_x2_kernel<<<dim3(F3DIM / 64, (T_STEPS * NB) / 128), 256, SMEM_BYTES>>>(W3, F3, H3, F3DIM, F2DIM);

    // Final linear + NonSpikingIF cumsum
    final_kernel<<<NB, F3DIM>>>(Wout, bout, out);
}